// round 14
// baseline (speedup 1.0000x reference)
#include <cuda_runtime.h>
#include <cstdint>

// SCE loss: softmax over C=128, signed per-(class,bin) histogram of
// p - onehot, then sum |.| / (B*C).
// Round 14: R13 + packed f32x2 arithmetic (sm_103a): exp prescale as
// 4x mul.f32x2, row-sum tree as add.f32x2, bin0 accumulate as 4x
// fma.f32x2. ex2.approx.ftz per element (same math as __expf).

namespace {
constexpr int kC       = 128;
constexpr int kBins    = 15;
constexpr int kSegs    = kC * kBins;   // 1920
constexpr int kBlocks  = 1184;
constexpr int kThreads = 256;
}

__device__ float    g_seg[kSegs];   // zero at load; last block re-zeroes
__device__ unsigned g_count;        // zero at load; last block re-zeroes

#define PACK2(out, lo, hi) \
    asm("mov.b64 %0, {%1, %2};" : "=l"(out) : "f"(lo), "f"(hi))
#define UNPACK2(lo, hi, in) \
    asm("mov.b64 {%0, %1}, %2;" : "=f"(lo), "=f"(hi) : "l"(in))
#define MUL2(out, a, b) \
    asm("mul.rn.f32x2 %0, %1, %2;" : "=l"(out) : "l"(a), "l"(b))
#define ADD2(out, a, b) \
    asm("add.rn.f32x2 %0, %1, %2;" : "=l"(out) : "l"(a), "l"(b))
#define FMA2(out, a, b, c) \
    asm("fma.rn.f32x2 %0, %1, %2, %3;" : "=l"(out) : "l"(a), "l"(b), "l"(c))

__device__ __forceinline__ float ex2f(float x) {
    float r;
    asm("ex2.approx.ftz.f32 %0, %1;" : "=f"(r) : "f"(x));
    return r;
}

__global__ void __launch_bounds__(kThreads, 8)
sce_kernel(const float* __restrict__ logits, const int* __restrict__ labels,
           int B, float* __restrict__ out, float scale)
{
    __shared__ float s[kSegs];
    for (int i = threadIdx.x; i < kSegs; i += blockDim.x) s[i] = 0.0f;
    __syncthreads();

    const int lane = threadIdx.x & 31;
    const int wpb  = blockDim.x >> 5;
    const int gw   = blockIdx.x * wpb + (threadIdx.x >> 5);
    const int nw   = gridDim.x * wpb;
    const int h    = lane >> 4;          // which row of the pair
    const int L    = lane & 15;
    const int c0   = L << 2;             // classes c0..c0+3 and 64+c0..64+c0+3

    const float kLog2e = 1.4426950408889634f;
    unsigned long long log2e2;           // (log2e, log2e)
    PACK2(log2e2, kLog2e, kLog2e);

    unsigned long long bin0p[4];         // packed accumulators (8 floats)
    #pragma unroll
    for (int q = 0; q < 4; q++) PACK2(bin0p[q], 0.0f, 0.0f);
    int cnt0 = 0, cnt1 = 0;              // packed byte counts: label in bin0
    float slowAdj[8] = {0,0,0,0,0,0,0,0};// rare-path subtractions from bin0

    int row0 = gw * 2;
    const float* rp = logits + (size_t)(row0 + h) * kC + c0;
    const int*   lp = labels + row0 + h;
    const size_t rstep = (size_t)nw * 2 * kC;
    const int    lstep = nw * 2;

    for (; row0 + 1 < B; row0 += lstep, rp += rstep, lp += lstep) {
        const int lab = __ldg(lp);
        const float4 va = __ldg(reinterpret_cast<const float4*>(rp));
        const float4 vb = __ldg(reinterpret_cast<const float4*>(rp + 64));

        // packed prescale by log2e, then scalar ex2
        unsigned long long p01, p23, p45, p67;
        PACK2(p01, va.x, va.y); PACK2(p23, va.z, va.w);
        PACK2(p45, vb.x, vb.y); PACK2(p67, vb.z, vb.w);
        MUL2(p01, p01, log2e2); MUL2(p23, p23, log2e2);
        MUL2(p45, p45, log2e2); MUL2(p67, p67, log2e2);

        float x0, x1, x2, x3, x4, x5, x6, x7;
        UNPACK2(x0, x1, p01); UNPACK2(x2, x3, p23);
        UNPACK2(x4, x5, p45); UNPACK2(x6, x7, p67);

        float e[8];
        e[0] = ex2f(x0); e[1] = ex2f(x1); e[2] = ex2f(x2); e[3] = ex2f(x3);
        e[4] = ex2f(x4); e[5] = ex2f(x5); e[6] = ex2f(x6); e[7] = ex2f(x7);

        // packed sum tree
        unsigned long long e01, e23, e45, e67, sA, sB, sAB;
        PACK2(e01, e[0], e[1]); PACK2(e23, e[2], e[3]);
        PACK2(e45, e[4], e[5]); PACK2(e67, e[6], e[7]);
        ADD2(sA, e01, e23); ADD2(sB, e45, e67); ADD2(sAB, sA, sB);
        float slo, shi;
        UNPACK2(slo, shi, sAB);
        float sm = slo + shi;
        #pragma unroll
        for (int o = 8; o > 0; o >>= 1)      // 4-level, within 16-lane half
            sm += __shfl_xor_sync(0xffffffffu, sm, o);

        const float inv    = __fdividef(1.0f, sm);
        const float thresh = sm * (1.0f / 15.0f);   // e > thresh <=> p > 1/15

        // packed provisional bin-0 accumulate: bin0 += e * inv
        unsigned long long inv2;
        PACK2(inv2, inv, inv);
        FMA2(bin0p[0], e01, inv2, bin0p[0]);
        FMA2(bin0p[1], e23, inv2, bin0p[1]);
        FMA2(bin0p[2], e45, inv2, bin0p[2]);
        FMA2(bin0p[3], e67, inv2, bin0p[3]);

        // label -1: register byte-counter on the owning lane (no atomic)
        const int  r     = lab & 63;
        const bool match = (L == (r >> 2));
        const int  jlab  = ((lab >> 6) << 2) | (r & 3);
        if (match) {
            if (jlab < 4) cnt0 += 1 << (8 * jlab);
            else          cnt1 += 1 << (8 * (jlab - 4));
        }

        // pair-gated fixups: each gate covers 2 elements (entry ~23%)
        #pragma unroll
        for (int q = 0; q < 4; q++) {
            if (fmaxf(e[2 * q], e[2 * q + 1]) > thresh) {
                #pragma unroll
                for (int t = 0; t < 2; t++) {
                    const int j = 2 * q + t;
                    if (e[j] > thresh) {
                        const float p = e[j] * inv;
                        int k = __float2int_ru(p * 15.0f) - 1; // ceil(15p)-1
                        k = min(k, kBins - 1);
                        float add = p;
                        if (match && j == jlab) {   // -1 moves with label
                            add = p - 1.0f;
                            if (j < 4) cnt0 -= 1 << (8 * j);
                            else       cnt1 -= 1 << (8 * (j - 4));
                        }
                        const int cls = (j < 4) ? (c0 + j) : (64 + c0 + j - 4);
                        atomicAdd(&s[cls * kBins + k], add);
                        slowAdj[j] += p;            // undo at flush time
                    }
                }
            }
        }
    }

    // odd-B tail: one row, h==0 half does the work (h==1 joins shuffles)
    if (row0 < B) {
        const float* trp = logits + (size_t)row0 * kC + c0;
        const int lab = __ldg(labels + row0);
        const float4 va = __ldg(reinterpret_cast<const float4*>(trp));
        const float4 vb = __ldg(reinterpret_cast<const float4*>(trp + 64));
        float e[8];
        e[0] = ex2f(va.x * kLog2e); e[1] = ex2f(va.y * kLog2e);
        e[2] = ex2f(va.z * kLog2e); e[3] = ex2f(va.w * kLog2e);
        e[4] = ex2f(vb.x * kLog2e); e[5] = ex2f(vb.y * kLog2e);
        e[6] = ex2f(vb.z * kLog2e); e[7] = ex2f(vb.w * kLog2e);
        float sm = 0.0f;
        #pragma unroll
        for (int j = 0; j < 8; j++) sm += e[j];
        #pragma unroll
        for (int o = 8; o > 0; o >>= 1)
            sm += __shfl_xor_sync(0xffffffffu, sm, o);
        if (h == 0) {
            const float inv = __fdividef(1.0f, sm);
            const int  r     = lab & 63;
            const bool match = (L == (r >> 2));
            const int  jlab  = ((lab >> 6) << 2) | (r & 3);
            #pragma unroll
            for (int j = 0; j < 8; j++) {
                const float p = e[j] * inv;
                int k = __float2int_ru(p * 15.0f) - 1;
                k = max(min(k, kBins - 1), 0);
                const bool isl = match && (j == jlab);
                const float add = isl ? (p - 1.0f) : p;
                const int cls = (j < 4) ? (c0 + j) : (64 + c0 + j - 4);
                atomicAdd(&s[cls * kBins + k], add);
            }
        }
    }

    // flush register accumulators into the block histogram
    #pragma unroll
    for (int q = 0; q < 4; q++) {
        float blo, bhi;
        UNPACK2(blo, bhi, bin0p[q]);
        const int j0 = 2 * q, j1 = 2 * q + 1;
        const int cls0 = (j0 < 4) ? (c0 + j0) : (64 + c0 + j0 - 4);
        const int cls1 = (j1 < 4) ? (c0 + j1) : (64 + c0 + j1 - 4);
        const int lc0 = (j0 < 4) ? ((cnt0 >> (8 * j0)) & 0xff)
                                 : ((cnt1 >> (8 * (j0 - 4))) & 0xff);
        const int lc1 = (j1 < 4) ? ((cnt0 >> (8 * j1)) & 0xff)
                                 : ((cnt1 >> (8 * (j1 - 4))) & 0xff);
        atomicAdd(&s[cls0 * kBins], blo - slowAdj[j0] - (float)lc0);
        atomicAdd(&s[cls1 * kBins], bhi - slowAdj[j1] - (float)lc1);
    }
    __syncthreads();

    // block histogram -> global
    for (int i = threadIdx.x; i < kSegs; i += blockDim.x) {
        const float v = s[i];
        if (v != 0.0f) atomicAdd(&g_seg[i], v);
    }

    // last-block finalize
    __shared__ bool isLast;
    __threadfence();
    if (threadIdx.x == 0)
        isLast = (atomicAdd(&g_count, 1u) == (unsigned)gridDim.x - 1u);
    __syncthreads();
    if (!isLast) return;

    __shared__ float red[32];
    float acc = 0.0f;
    for (int i = threadIdx.x; i < kSegs; i += blockDim.x) {
        acc += fabsf(__ldcg(&g_seg[i]));
        g_seg[i] = 0.0f;                   // reset for next replay
    }
    #pragma unroll
    for (int o = 16; o > 0; o >>= 1)
        acc += __shfl_xor_sync(0xffffffffu, acc, o);
    const int w = threadIdx.x >> 5;
    if (lane == 0) red[w] = acc;
    __syncthreads();
    if (w == 0) {
        const int nwarps = blockDim.x >> 5;
        acc = (lane < nwarps) ? red[lane] : 0.0f;
        #pragma unroll
        for (int o = 16; o > 0; o >>= 1)
            acc += __shfl_xor_sync(0xffffffffu, acc, o);
        if (threadIdx.x == 0) {
            out[0]  = acc * scale;
            g_count = 0u;                  // reset for next replay
        }
    }
}

extern "C" void kernel_launch(void* const* d_in, const int* in_sizes, int n_in,
                              void* d_out, int out_size) {
    const float* logits = (const float*)d_in[0];
    const int*   labels = (const int*)d_in[1];
    const int B = in_sizes[1];
    const float scale = 1.0f / ((float)B * (float)kC);
    sce_kernel<<<kBlocks, kThreads>>>(logits, labels, B, (float*)d_out, scale);
}

// round 15
// speedup vs baseline: 1.1435x; 1.1435x over previous
#include <cuda_runtime.h>

// SCE loss: softmax over C=128, signed per-(class,bin) histogram of
// p - onehot, then sum |.| / (B*C).
// Round 15: R13 + uniform pair gates (__ballot_sync makes the gate branch
// warp-uniform -> no BSSY/BSYNC divergence cost in the 77% not-taken case)
// + rcp.approx for the softmax normalization.

namespace {
constexpr int kC       = 128;
constexpr int kBins    = 15;
constexpr int kSegs    = kC * kBins;   // 1920
constexpr int kBlocks  = 1184;
constexpr int kThreads = 256;
}

__device__ float    g_seg[kSegs];   // zero at load; last block re-zeroes
__device__ unsigned g_count;        // zero at load; last block re-zeroes

__device__ __forceinline__ float frcp(float x) {
    float r;
    asm("rcp.approx.ftz.f32 %0, %1;" : "=f"(r) : "f"(x));
    return r;
}

__global__ void __launch_bounds__(kThreads, 8)
sce_kernel(const float* __restrict__ logits, const int* __restrict__ labels,
           int B, float* __restrict__ out, float scale)
{
    __shared__ float s[kSegs];
    for (int i = threadIdx.x; i < kSegs; i += blockDim.x) s[i] = 0.0f;
    __syncthreads();

    const int lane = threadIdx.x & 31;
    const int wpb  = blockDim.x >> 5;
    const int gw   = blockIdx.x * wpb + (threadIdx.x >> 5);
    const int nw   = gridDim.x * wpb;
    const int h    = lane >> 4;          // which row of the pair
    const int L    = lane & 15;
    const int c0   = L << 2;             // classes c0..c0+3 and 64+c0..64+c0+3

    float bin0[8] = {0,0,0,0,0,0,0,0};
    int cnt0 = 0, cnt1 = 0;              // packed byte counts: label in bin0

    int row0 = gw * 2;
    const float* rp = logits + (size_t)(row0 + h) * kC + c0;
    const int*   lp = labels + row0 + h;
    const size_t rstep = (size_t)nw * 2 * kC;
    const int    lstep = nw * 2;

    for (; row0 + 1 < B; row0 += lstep, rp += rstep, lp += lstep) {
        const int lab = __ldg(lp);
        // both LDG.128s fully coalesced: 16 lanes x 16B contiguous per row
        const float4 va = __ldg(reinterpret_cast<const float4*>(rp));
        const float4 vb = __ldg(reinterpret_cast<const float4*>(rp + 64));

        float e[8];
        e[0] = __expf(va.x); e[1] = __expf(va.y);
        e[2] = __expf(va.z); e[3] = __expf(va.w);
        e[4] = __expf(vb.x); e[5] = __expf(vb.y);
        e[6] = __expf(vb.z); e[7] = __expf(vb.w);

        float sm = ((e[0] + e[1]) + (e[2] + e[3]))
                 + ((e[4] + e[5]) + (e[6] + e[7]));
        #pragma unroll
        for (int o = 8; o > 0; o >>= 1)      // 4-level, within 16-lane half
            sm += __shfl_xor_sync(0xffffffffu, sm, o);

        const float inv    = frcp(sm);
        const float thresh = sm * (1.0f / 15.0f);   // e > thresh <=> p > 1/15

        #pragma unroll
        for (int j = 0; j < 8; j++)
            bin0[j] = fmaf(e[j], inv, bin0[j]);     // provisional bin 0

        // label -1: register byte-counter on the owning lane (no atomic)
        const int  r     = lab & 63;
        const bool match = (L == (r >> 2));
        const int  jlab  = ((lab >> 6) << 2) | (r & 3);
        if (match) {
            if (jlab < 4) cnt0 += 1 << (8 * jlab);
            else          cnt1 += 1 << (8 * (jlab - 4));
        }

        // pair-gated fixups, made WARP-UNIFORM via ballot (no divergence
        // in the ~77% not-taken case); entry ~23% per pair
        #pragma unroll
        for (int q = 0; q < 4; q++) {
            const bool hit = fmaxf(e[2 * q], e[2 * q + 1]) > thresh;
            if (__ballot_sync(0xffffffffu, hit)) {
                if (hit) {
                    #pragma unroll
                    for (int t = 0; t < 2; t++) {
                        const int j = 2 * q + t;
                        if (e[j] > thresh) {
                            const float p = e[j] * inv;
                            int k = __float2int_ru(p * 15.0f) - 1;
                            k = min(k, kBins - 1);
                            float add = p;
                            if (match && j == jlab) {   // -1 moves with label
                                add = p - 1.0f;
                                if (j < 4) cnt0 -= 1 << (8 * j);
                                else       cnt1 -= 1 << (8 * (j - 4));
                            }
                            const int cls = (j < 4) ? (c0 + j)
                                                    : (64 + c0 + j - 4);
                            atomicAdd(&s[cls * kBins + k], add);
                            bin0[j] -= p;               // undo provisional add
                        }
                    }
                }
            }
        }
    }

    // odd-B tail: one row, h==0 half does the work (h==1 joins shuffles)
    if (row0 < B) {
        const float* trp = logits + (size_t)row0 * kC + c0;
        const int lab = __ldg(labels + row0);
        const float4 va = __ldg(reinterpret_cast<const float4*>(trp));
        const float4 vb = __ldg(reinterpret_cast<const float4*>(trp + 64));
        float e[8];
        e[0] = __expf(va.x); e[1] = __expf(va.y);
        e[2] = __expf(va.z); e[3] = __expf(va.w);
        e[4] = __expf(vb.x); e[5] = __expf(vb.y);
        e[6] = __expf(vb.z); e[7] = __expf(vb.w);
        float sm = 0.0f;
        #pragma unroll
        for (int j = 0; j < 8; j++) sm += e[j];
        #pragma unroll
        for (int o = 8; o > 0; o >>= 1)
            sm += __shfl_xor_sync(0xffffffffu, sm, o);
        if (h == 0) {
            const float inv = frcp(sm);
            const int  r     = lab & 63;
            const bool match = (L == (r >> 2));
            const int  jlab  = ((lab >> 6) << 2) | (r & 3);
            #pragma unroll
            for (int j = 0; j < 8; j++) {
                const float p = e[j] * inv;
                int k = __float2int_ru(p * 15.0f) - 1;
                k = max(min(k, kBins - 1), 0);
                const bool isl = match && (j == jlab);
                const float add = isl ? (p - 1.0f) : p;
                const int cls = (j < 4) ? (c0 + j) : (64 + c0 + j - 4);
                atomicAdd(&s[cls * kBins + k], add);
            }
        }
    }

    // flush register accumulators into the block histogram
    #pragma unroll
    for (int j = 0; j < 8; j++) {
        const int lc = (j < 4) ? ((cnt0 >> (8 * j)) & 0xff)
                               : ((cnt1 >> (8 * (j - 4))) & 0xff);
        const int cls = (j < 4) ? (c0 + j) : (64 + c0 + j - 4);
        atomicAdd(&s[cls * kBins], bin0[j] - (float)lc);
    }
    __syncthreads();

    // block histogram -> global
    for (int i = threadIdx.x; i < kSegs; i += blockDim.x) {
        const float v = s[i];
        if (v != 0.0f) atomicAdd(&g_seg[i], v);
    }

    // last-block finalize
    __shared__ bool isLast;
    __threadfence();
    if (threadIdx.x == 0)
        isLast = (atomicAdd(&g_count, 1u) == (unsigned)gridDim.x - 1u);
    __syncthreads();
    if (!isLast) return;

    __shared__ float red[32];
    float acc = 0.0f;
    for (int i = threadIdx.x; i < kSegs; i += blockDim.x) {
        acc += fabsf(__ldcg(&g_seg[i]));
        g_seg[i] = 0.0f;                   // reset for next replay
    }
    #pragma unroll
    for (int o = 16; o > 0; o >>= 1)
        acc += __shfl_xor_sync(0xffffffffu, acc, o);
    const int w = threadIdx.x >> 5;
    if (lane == 0) red[w] = acc;
    __syncthreads();
    if (w == 0) {
        const int nwarps = blockDim.x >> 5;
        acc = (lane < nwarps) ? red[lane] : 0.0f;
        #pragma unroll
        for (int o = 16; o > 0; o >>= 1)
            acc += __shfl_xor_sync(0xffffffffu, acc, o);
        if (threadIdx.x == 0) {
            out[0]  = acc * scale;
            g_count = 0u;                  // reset for next replay
        }
    }
}

extern "C" void kernel_launch(void* const* d_in, const int* in_sizes, int n_in,
                              void* d_out, int out_size) {
    const float* logits = (const float*)d_in[0];
    const int*   labels = (const int*)d_in[1];
    const int B = in_sizes[1];
    const float scale = 1.0f / ((float)B * (float)kC);
    sce_kernel<<<kBlocks, kThreads>>>(logits, labels, B, (float*)d_out, scale);
}

// round 16
// speedup vs baseline: 1.1860x; 1.0372x over previous
#include <cuda_runtime.h>

// SCE loss: softmax over C=128, signed per-(class,bin) histogram of
// p - onehot, then sum |.| / (B*C).
// Round 16: R13 (best: 60.3us) with final micro-trims: rcp.approx for the
// normalization, label jlab computation deferred into the rare fixup body,
// leaner byte-counter update. No structural changes.

namespace {
constexpr int kC       = 128;
constexpr int kBins    = 15;
constexpr int kSegs    = kC * kBins;   // 1920
constexpr int kBlocks  = 1184;
constexpr int kThreads = 256;
}

__device__ float    g_seg[kSegs];   // zero at load; last block re-zeroes
__device__ unsigned g_count;        // zero at load; last block re-zeroes

__device__ __forceinline__ float frcp(float x) {
    float r;
    asm("rcp.approx.ftz.f32 %0, %1;" : "=f"(r) : "f"(x));
    return r;
}

__global__ void __launch_bounds__(kThreads, 8)
sce_kernel(const float* __restrict__ logits, const int* __restrict__ labels,
           int B, float* __restrict__ out, float scale)
{
    __shared__ float s[kSegs];
    for (int i = threadIdx.x; i < kSegs; i += blockDim.x) s[i] = 0.0f;
    __syncthreads();

    const int lane = threadIdx.x & 31;
    const int wpb  = blockDim.x >> 5;
    const int gw   = blockIdx.x * wpb + (threadIdx.x >> 5);
    const int nw   = gridDim.x * wpb;
    const int h    = lane >> 4;          // which row of the pair
    const int L    = lane & 15;
    const int c0   = L << 2;             // classes c0..c0+3 and 64+c0..64+c0+3

    float bin0[8] = {0,0,0,0,0,0,0,0};
    int cnt0 = 0, cnt1 = 0;              // packed byte counts: label in bin0

    int row0 = gw * 2;
    const float* rp = logits + (size_t)(row0 + h) * kC + c0;
    const int*   lp = labels + row0 + h;
    const size_t rstep = (size_t)nw * 2 * kC;
    const int    lstep = nw * 2;

    for (; row0 + 1 < B; row0 += lstep, rp += rstep, lp += lstep) {
        const int lab = __ldg(lp);
        // both LDG.128s fully coalesced: 16 lanes x 16B contiguous per row
        const float4 va = __ldg(reinterpret_cast<const float4*>(rp));
        const float4 vb = __ldg(reinterpret_cast<const float4*>(rp + 64));

        float e[8];
        e[0] = __expf(va.x); e[1] = __expf(va.y);
        e[2] = __expf(va.z); e[3] = __expf(va.w);
        e[4] = __expf(vb.x); e[5] = __expf(vb.y);
        e[6] = __expf(vb.z); e[7] = __expf(vb.w);

        float sm = ((e[0] + e[1]) + (e[2] + e[3]))
                 + ((e[4] + e[5]) + (e[6] + e[7]));
        #pragma unroll
        for (int o = 8; o > 0; o >>= 1)      // 4-level, within 16-lane half
            sm += __shfl_xor_sync(0xffffffffu, sm, o);

        const float inv    = frcp(sm);
        const float thresh = sm * (1.0f / 15.0f);   // e > thresh <=> p > 1/15

        #pragma unroll
        for (int j = 0; j < 8; j++)
            bin0[j] = fmaf(e[j], inv, bin0[j]);     // provisional bin 0

        // label -1: register byte-counter on the owning lane (no atomic).
        // jlab NOT computed here -- deferred to the rare fixup body.
        const bool match = (L == ((lab & 63) >> 2));
        if (match) {
            const int sh = (((lab >> 6) << 2) | (lab & 3)) * 8;  // 8*jlab
            if (sh < 32) cnt0 += 1 << sh;
            else         cnt1 += 1 << (sh - 32);
        }

        // pair-gated fixups: each gate covers 2 elements (entry ~23%)
        #pragma unroll
        for (int q = 0; q < 4; q++) {
            if (fmaxf(e[2 * q], e[2 * q + 1]) > thresh) {
                const int jlab = ((lab >> 6) << 2) | (lab & 3);
                #pragma unroll
                for (int t = 0; t < 2; t++) {
                    const int j = 2 * q + t;
                    if (e[j] > thresh) {
                        const float p = e[j] * inv;
                        int k = __float2int_ru(p * 15.0f) - 1; // ceil(15p)-1
                        k = min(k, kBins - 1);
                        float add = p;
                        if (match && j == jlab) {   // -1 moves with label
                            add = p - 1.0f;
                            if (j < 4) cnt0 -= 1 << (8 * j);
                            else       cnt1 -= 1 << (8 * (j - 4));
                        }
                        const int cls = (j < 4) ? (c0 + j) : (64 + c0 + j - 4);
                        atomicAdd(&s[cls * kBins + k], add);
                        bin0[j] -= p;               // undo provisional add
                    }
                }
            }
        }
    }

    // odd-B tail: one row, h==0 half does the work (h==1 joins shuffles)
    if (row0 < B) {
        const float* trp = logits + (size_t)row0 * kC + c0;
        const int lab = __ldg(labels + row0);
        const float4 va = __ldg(reinterpret_cast<const float4*>(trp));
        const float4 vb = __ldg(reinterpret_cast<const float4*>(trp + 64));
        float e[8];
        e[0] = __expf(va.x); e[1] = __expf(va.y);
        e[2] = __expf(va.z); e[3] = __expf(va.w);
        e[4] = __expf(vb.x); e[5] = __expf(vb.y);
        e[6] = __expf(vb.z); e[7] = __expf(vb.w);
        float sm = 0.0f;
        #pragma unroll
        for (int j = 0; j < 8; j++) sm += e[j];
        #pragma unroll
        for (int o = 8; o > 0; o >>= 1)
            sm += __shfl_xor_sync(0xffffffffu, sm, o);
        if (h == 0) {
            const float inv = frcp(sm);
            const bool match = (L == ((lab & 63) >> 2));
            const int  jlab  = ((lab >> 6) << 2) | (lab & 3);
            #pragma unroll
            for (int j = 0; j < 8; j++) {
                const float p = e[j] * inv;
                int k = __float2int_ru(p * 15.0f) - 1;
                k = max(min(k, kBins - 1), 0);
                const bool isl = match && (j == jlab);
                const float add = isl ? (p - 1.0f) : p;
                const int cls = (j < 4) ? (c0 + j) : (64 + c0 + j - 4);
                atomicAdd(&s[cls * kBins + k], add);
            }
        }
    }

    // flush register accumulators into the block histogram
    #pragma unroll
    for (int j = 0; j < 8; j++) {
        const int lc = (j < 4) ? ((cnt0 >> (8 * j)) & 0xff)
                               : ((cnt1 >> (8 * (j - 4))) & 0xff);
        const int cls = (j < 4) ? (c0 + j) : (64 + c0 + j - 4);
        atomicAdd(&s[cls * kBins], bin0[j] - (float)lc);
    }
    __syncthreads();

    // block histogram -> global
    for (int i = threadIdx.x; i < kSegs; i += blockDim.x) {
        const float v = s[i];
        if (v != 0.0f) atomicAdd(&g_seg[i], v);
    }

    // last-block finalize
    __shared__ bool isLast;
    __threadfence();
    if (threadIdx.x == 0)
        isLast = (atomicAdd(&g_count, 1u) == (unsigned)gridDim.x - 1u);
    __syncthreads();
    if (!isLast) return;

    __shared__ float red[32];
    float acc = 0.0f;
    for (int i = threadIdx.x; i < kSegs; i += blockDim.x) {
        acc += fabsf(__ldcg(&g_seg[i]));
        g_seg[i] = 0.0f;                   // reset for next replay
    }
    #pragma unroll
    for (int o = 16; o > 0; o >>= 1)
        acc += __shfl_xor_sync(0xffffffffu, acc, o);
    const int w = threadIdx.x >> 5;
    if (lane == 0) red[w] = acc;
    __syncthreads();
    if (w == 0) {
        const int nwarps = blockDim.x >> 5;
        acc = (lane < nwarps) ? red[lane] : 0.0f;
        #pragma unroll
        for (int o = 16; o > 0; o >>= 1)
            acc += __shfl_xor_sync(0xffffffffu, acc, o);
        if (threadIdx.x == 0) {
            out[0]  = acc * scale;
            g_count = 0u;                  // reset for next replay
        }
    }
}

extern "C" void kernel_launch(void* const* d_in, const int* in_sizes, int n_in,
                              void* d_out, int out_size) {
    const float* logits = (const float*)d_in[0];
    const int*   labels = (const int*)d_in[1];
    const int B = in_sizes[1];
    const float scale = 1.0f / ((float)B * (float)kC);
    sce_kernel<<<kBlocks, kThreads>>>(logits, labels, B, (float*)d_out, scale);
}

// round 17
// speedup vs baseline: 1.2352x; 1.0414x over previous
#include <cuda_runtime.h>

// SCE loss: softmax over C=128, signed per-(class,bin) histogram of
// p - onehot, then sum |.| / (B*C).
// Round 17: R13 body verbatim (best: 60.3us), reshaped grid: 512 threads x
// 592 blocks (4 blocks/SM x 16 warps = same 64 warps/SM) -> half the block
// histograms: half the shared-init, half the global-flush atomics, half
// the finalize drain.

namespace {
constexpr int kC       = 128;
constexpr int kBins    = 15;
constexpr int kSegs    = kC * kBins;   // 1920
constexpr int kBlocks  = 592;          // 4 blocks/SM x 148 SMs
constexpr int kThreads = 512;
}

__device__ float    g_seg[kSegs];   // zero at load; last block re-zeroes
__device__ unsigned g_count;        // zero at load; last block re-zeroes

__global__ void __launch_bounds__(kThreads, 4)
sce_kernel(const float* __restrict__ logits, const int* __restrict__ labels,
           int B, float* __restrict__ out, float scale)
{
    __shared__ float s[kSegs];
    for (int i = threadIdx.x; i < kSegs; i += blockDim.x) s[i] = 0.0f;
    __syncthreads();

    const int lane = threadIdx.x & 31;
    const int wpb  = blockDim.x >> 5;
    const int gw   = blockIdx.x * wpb + (threadIdx.x >> 5);
    const int nw   = gridDim.x * wpb;
    const int h    = lane >> 4;          // which row of the pair
    const int L    = lane & 15;
    const int c0   = L << 2;             // classes c0..c0+3 and 64+c0..64+c0+3

    float bin0[8] = {0,0,0,0,0,0,0,0};
    int cnt0 = 0, cnt1 = 0;              // packed byte counts: label in bin0

    int row0 = gw * 2;
    const float* rp = logits + (size_t)(row0 + h) * kC + c0;
    const int*   lp = labels + row0 + h;
    const size_t rstep = (size_t)nw * 2 * kC;
    const int    lstep = nw * 2;

    for (; row0 + 1 < B; row0 += lstep, rp += rstep, lp += lstep) {
        const int lab = __ldg(lp);
        // both LDG.128s fully coalesced: 16 lanes x 16B contiguous per row
        const float4 va = __ldg(reinterpret_cast<const float4*>(rp));
        const float4 vb = __ldg(reinterpret_cast<const float4*>(rp + 64));

        float e[8];
        e[0] = __expf(va.x); e[1] = __expf(va.y);
        e[2] = __expf(va.z); e[3] = __expf(va.w);
        e[4] = __expf(vb.x); e[5] = __expf(vb.y);
        e[6] = __expf(vb.z); e[7] = __expf(vb.w);

        float sm = ((e[0] + e[1]) + (e[2] + e[3]))
                 + ((e[4] + e[5]) + (e[6] + e[7]));
        #pragma unroll
        for (int o = 8; o > 0; o >>= 1)      // 4-level, within 16-lane half
            sm += __shfl_xor_sync(0xffffffffu, sm, o);

        const float inv    = __fdividef(1.0f, sm);
        const float thresh = sm * (1.0f / 15.0f);   // e > thresh <=> p > 1/15

        #pragma unroll
        for (int j = 0; j < 8; j++)
            bin0[j] = fmaf(e[j], inv, bin0[j]);     // provisional bin 0

        // label -1: register byte-counter on the owning lane (no atomic)
        const int  r     = lab & 63;
        const bool match = (L == (r >> 2));
        const int  jlab  = ((lab >> 6) << 2) | (r & 3);
        if (match) {
            if (jlab < 4) cnt0 += 1 << (8 * jlab);
            else          cnt1 += 1 << (8 * (jlab - 4));
        }

        // pair-gated fixups: each gate covers 2 elements (entry ~23%)
        #pragma unroll
        for (int q = 0; q < 4; q++) {
            if (fmaxf(e[2 * q], e[2 * q + 1]) > thresh) {
                #pragma unroll
                for (int t = 0; t < 2; t++) {
                    const int j = 2 * q + t;
                    if (e[j] > thresh) {
                        const float p = e[j] * inv;
                        int k = __float2int_ru(p * 15.0f) - 1; // ceil(15p)-1
                        k = min(k, kBins - 1);
                        float add = p;
                        if (match && j == jlab) {   // -1 moves with label
                            add = p - 1.0f;
                            if (j < 4) cnt0 -= 1 << (8 * j);
                            else       cnt1 -= 1 << (8 * (j - 4));
                        }
                        const int cls = (j < 4) ? (c0 + j) : (64 + c0 + j - 4);
                        atomicAdd(&s[cls * kBins + k], add);
                        bin0[j] -= p;               // undo provisional add
                    }
                }
            }
        }
    }

    // odd-B tail: one row, h==0 half does the work (h==1 joins shuffles)
    if (row0 < B) {
        const float* trp = logits + (size_t)row0 * kC + c0;
        const int lab = __ldg(labels + row0);
        const float4 va = __ldg(reinterpret_cast<const float4*>(trp));
        const float4 vb = __ldg(reinterpret_cast<const float4*>(trp + 64));
        float e[8];
        e[0] = __expf(va.x); e[1] = __expf(va.y);
        e[2] = __expf(va.z); e[3] = __expf(va.w);
        e[4] = __expf(vb.x); e[5] = __expf(vb.y);
        e[6] = __expf(vb.z); e[7] = __expf(vb.w);
        float sm = 0.0f;
        #pragma unroll
        for (int j = 0; j < 8; j++) sm += e[j];
        #pragma unroll
        for (int o = 8; o > 0; o >>= 1)
            sm += __shfl_xor_sync(0xffffffffu, sm, o);
        if (h == 0) {
            const float inv = __fdividef(1.0f, sm);
            const int  r     = lab & 63;
            const bool match = (L == (r >> 2));
            const int  jlab  = ((lab >> 6) << 2) | (r & 3);
            #pragma unroll
            for (int j = 0; j < 8; j++) {
                const float p = e[j] * inv;
                int k = __float2int_ru(p * 15.0f) - 1;
                k = max(min(k, kBins - 1), 0);
                const bool isl = match && (j == jlab);
                const float add = isl ? (p - 1.0f) : p;
                const int cls = (j < 4) ? (c0 + j) : (64 + c0 + j - 4);
                atomicAdd(&s[cls * kBins + k], add);
            }
        }
    }

    // flush register accumulators into the block histogram
    #pragma unroll
    for (int j = 0; j < 8; j++) {
        const int lc = (j < 4) ? ((cnt0 >> (8 * j)) & 0xff)
                               : ((cnt1 >> (8 * (j - 4))) & 0xff);
        const int cls = (j < 4) ? (c0 + j) : (64 + c0 + j - 4);
        atomicAdd(&s[cls * kBins], bin0[j] - (float)lc);
    }
    __syncthreads();

    // block histogram -> global
    for (int i = threadIdx.x; i < kSegs; i += blockDim.x) {
        const float v = s[i];
        if (v != 0.0f) atomicAdd(&g_seg[i], v);
    }

    // last-block finalize
    __shared__ bool isLast;
    __threadfence();
    if (threadIdx.x == 0)
        isLast = (atomicAdd(&g_count, 1u) == (unsigned)gridDim.x - 1u);
    __syncthreads();
    if (!isLast) return;

    __shared__ float red[32];
    float acc = 0.0f;
    for (int i = threadIdx.x; i < kSegs; i += blockDim.x) {
        acc += fabsf(__ldcg(&g_seg[i]));
        g_seg[i] = 0.0f;                   // reset for next replay
    }
    #pragma unroll
    for (int o = 16; o > 0; o >>= 1)
        acc += __shfl_xor_sync(0xffffffffu, acc, o);
    const int w = threadIdx.x >> 5;
    if (lane == 0) red[w] = acc;
    __syncthreads();
    if (w == 0) {
        const int nwarps = blockDim.x >> 5;
        acc = (lane < nwarps) ? red[lane] : 0.0f;
        #pragma unroll
        for (int o = 16; o > 0; o >>= 1)
            acc += __shfl_xor_sync(0xffffffffu, acc, o);
        if (threadIdx.x == 0) {
            out[0]  = acc * scale;
            g_count = 0u;                  // reset for next replay
        }
    }
}

extern "C" void kernel_launch(void* const* d_in, const int* in_sizes, int n_in,
                              void* d_out, int out_size) {
    const float* logits = (const float*)d_in[0];
    const int*   labels = (const int*)d_in[1];
    const int B = in_sizes[1];
    const float scale = 1.0f / ((float)B * (float)kC);
    sce_kernel<<<kBlocks, kThreads>>>(logits, labels, B, (float*)d_out, scale);
}